// round 14
// baseline (speedup 1.0000x reference)
#include <cuda_runtime.h>
#include <cuda_fp16.h>
#include <cstdint>

// Problem constants: B=4, N=1024, C=16, H=W=128
#define BB 4
#define NN 1024
#define CC 16
#define HW 128

// f16 separable factors over COMPACT slots: ev [b][gv][slot], euT [b][gu][slot]
__device__ unsigned short g_ev [BB * HW * NN];
__device__ unsigned short g_euT[BB * HW * NN];
__device__ int g_pidx[BB * NN];
__device__ int g_cnt[BB];

__device__ __forceinline__ float ex2f(float x) {
    float y;
    asm("ex2.approx.ftz.f32 %0, %1;" : "=f"(y) : "f"(x));
    return y;
}

__device__ __forceinline__ uint32_t smem_u32(const void* p) {
    uint32_t a;
    asm("{ .reg .u64 t; cvta.to.shared.u64 t, %1; cvt.u32.u64 %0, t; }"
        : "=r"(a) : "l"(p));
    return a;
}

__device__ __forceinline__ uint32_t hmul2(uint32_t a, uint32_t b) {
    uint32_t d;
    asm("mul.rn.f16x2 %0, %1, %2;" : "=r"(d) : "r"(a), "r"(b));
    return d;
}

__device__ __forceinline__ void ldsm_x4(uint32_t* r, uint32_t addr) {
    asm volatile("ldmatrix.sync.aligned.m8n8.x4.shared.b16 {%0,%1,%2,%3}, [%4];"
                 : "=r"(r[0]), "=r"(r[1]), "=r"(r[2]), "=r"(r[3]) : "r"(addr));
}

__device__ __forceinline__ void mma16816(float* d, const uint32_t* a,
                                         const uint32_t* b) {
    asm volatile(
        "mma.sync.aligned.m16n8k16.row.col.f32.f16.f16.f32 "
        "{%0,%1,%2,%3}, {%4,%5,%6,%7}, {%8,%9}, {%0,%1,%2,%3};"
        : "+f"(d[0]), "+f"(d[1]), "+f"(d[2]), "+f"(d[3])
        : "r"(a[0]), "r"(a[1]), "r"(a[2]), "r"(a[3]), "r"(b[0]), "r"(b[1]));
}

// ---------------------------------------------------------------------------
// Kernel F: fused projection + compaction + factor write.
// grid = BB*16 blocks x 128 threads. Each block:
//   1. prefetches ALL 1024 points of its batch (8 groups/thread, MLP)
//   2. runs the deterministic ballot/prefix compaction (identical in every
//      block of the batch -> identical slots; blk 0 publishes pidx/cnt)
//   3. writes its 8 ev rows (gv = blk*8..+8) and 8 euT rows (same indices)
// ---------------------------------------------------------------------------
__global__ void __launch_bounds__(128) fused_proj_kernel(
    const float* __restrict__ Kc,
    const float* __restrict__ RT,
    const float* __restrict__ pts3d,
    const float* __restrict__ scale)
{
    const int b   = blockIdx.x >> 4;
    const int blk = blockIdx.x & 15;
    const int t    = threadIdx.x;
    const int wid  = t >> 5;
    const int lane = t & 31;

    __shared__ float su[NN], sv[NN], ssv[NN];
    __shared__ int wcnt[4];

    // broadcast camera params
    const float k0 = Kc[0], k1 = Kc[1], k2 = Kc[2];
    const float k3 = Kc[3], k4 = Kc[4], k5 = Kc[5];
    const float k6 = Kc[6], k7 = Kc[7], k8 = Kc[8];
    const float* rt = RT + b * 12;
    const float r0 = rt[0], r1 = rt[1], r2 = rt[2],  r3  = rt[3];
    const float r4 = rt[4], r5 = rt[5], r6 = rt[6],  r7  = rt[7];
    const float r8 = rt[8], r9 = rt[9], r10 = rt[10], r11 = rt[11];

    // prefetch all 8 point groups (latency paid once)
    float px[8], py[8], pz[8], sc[8];
    #pragma unroll
    for (int i = 0; i < 8; i++) {
        const float* p = pts3d + ((size_t)b * NN + i * 128 + t) * 3;
        px[i] = p[0]; py[i] = p[1]; pz[i] = p[2];
        sc[i] = scale[b * NN + i * 128 + t];
    }

    int base = 0;
    #pragma unroll
    for (int i = 0; i < 8; i++) {
        float l0 = r0 * px[i] + r1 * py[i] + r2  * pz[i] + r3;
        float l1 = r4 * px[i] + r5 * py[i] + r6  * pz[i] + r7;
        float l2 = r8 * px[i] + r9 * py[i] + r10 * pz[i] + r11;
        float x = k0 * l0 + k1 * l1 + k2 * l2;
        float y = k3 * l0 + k4 * l1 + k5 * l2;
        float z = k6 * l0 + k7 * l1 + k8 * l2;
        float zc = fmaxf(z, 0.1f);
        float u = x / zc, v = y / zc;
        float sig = k0 * 0.03125f;                 // sigma = K[0,0]/32
        float s = sc[i] * sig * sig;
        float tt = sqrtf(17.5f * s);               // f16-exact-zero radius
        bool keep = (z > 0.1f) && (u > -tt) && (u < 127.0f + tt)
                               && (v > -tt) && (v < 127.0f + tt);

        unsigned bal = __ballot_sync(0xffffffffu, keep);
        if (lane == 0) wcnt[wid] = __popc(bal);
        __syncthreads();
        int off = base;
        #pragma unroll
        for (int w = 0; w < 4; w++) if (w < wid) off += wcnt[w];
        const int tot = wcnt[0] + wcnt[1] + wcnt[2] + wcnt[3];
        if (keep) {
            const int slot = off + __popc(bal & ((1u << lane) - 1));
            su[slot]  = u;
            sv[slot]  = v;
            ssv[slot] = -1.4426950408889634f / s;  // -log2(e)/s
            if (blk == 0) g_pidx[b * NN + slot] = i * 128 + t;
        }
        base += tot;
        __syncthreads();
    }
    const int cnt = base;
    if (blk == 0 && t == 0) g_cnt[b] = cnt;
    const int pad = (cnt + 63) & ~63;

    // write 8 ev rows + 8 euT rows (same row indices; zeros for pad slots)
    #pragma unroll 1
    for (int r = 0; r < 8; r++) {
        const int g = blk * 8 + r;
        unsigned short* dv = g_ev  + (size_t)(b * HW + g) * NN;
        unsigned short* du = g_euT + (size_t)(b * HW + g) * NN;
        const float fg = (float)g;
        for (int s2 = t; s2 < pad; s2 += 128) {
            float hv = 0.0f, hu = 0.0f;
            if (s2 < cnt) {
                float dvv = sv[s2] - fg;
                hv = ex2f(dvv * dvv * ssv[s2]);
                float duu = su[s2] - fg;
                hu = ex2f(duu * duu * ssv[s2]);
            }
            dv[s2] = __half_as_ushort(__float2half(hv));
            du[s2] = __half_as_ushort(__float2half(hu));
        }
    }
}

// ---------------------------------------------------------------------------
// Kernel B: HMMA GEMM over COMPACT K (unchanged from R13).
// ---------------------------------------------------------------------------
#define EU_STRIDE 72
#define FT_STRIDE 1032
#define SEU_OFF   0u                       // 2 x 128 x 72 x 2B = 36864
#define SFT_OFF   36864u                   // 16 x 1032 x 2B   = 33024
#define SEV_OFF   69888u                   // 4 x 1024 x 2B    =  8192
#define SMEM_DYN  78592u

__global__ void __launch_bounds__(512, 1) accum_kernel(
    const float* __restrict__ feat,
    float* __restrict__ out)
{
    extern __shared__ __align__(16) char smem[];
    unsigned short* sft = (unsigned short*)(smem + SFT_OFF);
    unsigned short* sev = (unsigned short*)(smem + SEV_OFF);

    const int b   = blockIdx.x >> 5;
    const int gv0 = (blockIdx.x & 31) << 2;
    const int t    = threadIdx.x;
    const int wid  = t >> 5;
    const int lane = t & 31;

    const int cnt = g_cnt[b];
    const int pad = (cnt + 63) & ~63;
    const int nch = pad >> 6;

    // ---- stage featT via idx gather (zeros for pad slots) ----
    {
        const int c = t & 15;
        for (int s = t >> 4; s < pad; s += 32) {
            float v = 0.0f;
            if (s < cnt)
                v = feat[((size_t)b * NN + g_pidx[b * NN + s]) * CC + c];
            sft[c * FT_STRIDE + s] = __half_as_ushort(__float2half(v));
        }
    }
    // ---- stage ev rows ----
    {
        const int r  = t >> 7;
        const int i8 = (t & 127) * 8;
        if (i8 < pad)
            *(uint4*)&sev[r * 1024 + i8] =
                *(const uint4*)(g_ev + (size_t)(b * HW + gv0 + r) * NN + i8);
    }

    // eu staging mapping: 4 threads per gu row, 16 halfwords (32B) each
    const int srow = t >> 2;
    const int sq   = (t & 3) * 16;
    const unsigned short* esrc = g_euT + (size_t)(b * HW + srow) * NN + sq;
    unsigned short* edst =
        (unsigned short*)(smem + SEU_OFF) + srow * EU_STRIDE + sq;

    if (nch > 0) {
        const uint4 p0 = *(const uint4*)esrc;
        const uint4 p1 = *(const uint4*)(esrc + 8);
        *(uint4*)edst       = p0;
        *(uint4*)(edst + 8) = p1;
    }
    __syncthreads();

    // consumer mapping
    const int mt = wid & 7;
    const int rp = wid >> 3;
    const int c0 = (lane & 3) * 2;

    const unsigned short* evr0 = sev + (rp * 2) * 1024;
    const unsigned short* evr1 = evr0 + 1024;

    const uint32_t sbase = smem_u32(smem);
    const uint32_t euLm0 = sbase + SEU_OFF +
        (uint32_t)(((mt * 16 + (lane & 15)) * EU_STRIDE + (lane >> 4) * 8) * 2);
    const uint32_t ftLm0 = sbase + SFT_OFF +
        (uint32_t)((((lane & 15)) * FT_STRIDE + (lane >> 4) * 8) * 2);

    float acc[2][2][4];
    #pragma unroll
    for (int rr = 0; rr < 2; rr++)
        #pragma unroll
        for (int nt = 0; nt < 2; nt++)
            #pragma unroll
            for (int q = 0; q < 4; q++) acc[rr][nt][q] = 0.0f;

    #pragma unroll 1
    for (int k = 0; k < nch; k++) {
        const int nb = k * 64;
        uint4 p0, p1;
        if (k + 1 < nch) {
            const unsigned short* s = esrc + (size_t)(nb + 64);
            p0 = *(const uint4*)s;
            p1 = *(const uint4*)(s + 8);
        }

        const uint32_t euLm = euLm0 + (uint32_t)(k & 1) * (128 * EU_STRIDE * 2);
        const uint32_t ftLm = ftLm0 + (uint32_t)(nb * 2);

        #pragma unroll
        for (int ks = 0; ks < 4; ks++) {
            const int nA = nb + ks * 16 + c0;
            const int nB = nA + 8;

            const uint32_t e0A = *(const uint32_t*)(evr0 + nA);
            const uint32_t e0B = *(const uint32_t*)(evr0 + nB);
            const uint32_t e1A = *(const uint32_t*)(evr1 + nA);
            const uint32_t e1B = *(const uint32_t*)(evr1 + nB);

            uint32_t u[4];
            ldsm_x4(u, euLm + (uint32_t)(ks * 32));

            uint32_t f[4];
            ldsm_x4(f, ftLm + (uint32_t)(ks * 32));
            uint32_t bf0[2] = { f[0], f[2] };
            uint32_t bf1[2] = { f[1], f[3] };

            uint32_t a0[4] = { hmul2(e0A, u[0]), hmul2(e0A, u[1]),
                               hmul2(e0B, u[2]), hmul2(e0B, u[3]) };
            mma16816(acc[0][0], a0, bf0);
            mma16816(acc[0][1], a0, bf1);

            uint32_t a1[4] = { hmul2(e1A, u[0]), hmul2(e1A, u[1]),
                               hmul2(e1B, u[2]), hmul2(e1B, u[3]) };
            mma16816(acc[1][0], a1, bf0);
            mma16816(acc[1][1], a1, bf1);
        }

        if (k + 1 < nch) {
            unsigned short* d = edst + ((k + 1) & 1) * (128 * EU_STRIDE);
            *(uint4*)d       = p0;
            *(uint4*)(d + 8) = p1;
        }
        __syncthreads();
    }

    // ---- epilogue: D[gu][c] -> out[b][c][gv][gu] ----
    {
        const int guw = mt * 16 + (lane >> 2);
        const int c0w = (lane & 3) * 2;
        #pragma unroll
        for (int rr = 0; rr < 2; rr++) {
            const int gv = gv0 + rp * 2 + rr;
            float* ob = out + (size_t)b * CC * HW * HW + (size_t)gv * HW;
            #pragma unroll
            for (int nt = 0; nt < 2; nt++) {
                const int c = nt * 8 + c0w;
                ob[(size_t)c * HW * HW + guw]           = acc[rr][nt][0];
                ob[(size_t)(c + 1) * HW * HW + guw]     = acc[rr][nt][1];
                ob[(size_t)c * HW * HW + guw + 8]       = acc[rr][nt][2];
                ob[(size_t)(c + 1) * HW * HW + guw + 8] = acc[rr][nt][3];
            }
        }
    }
}

extern "C" void kernel_launch(void* const* d_in, const int* in_sizes, int n_in,
                              void* d_out, int out_size)
{
    const float* Kc    = (const float*)d_in[0];
    const float* RT    = (const float*)d_in[1];
    const float* pts3d = (const float*)d_in[2];
    const float* feat  = (const float*)d_in[3];
    const float* scale = (const float*)d_in[4];
    float* out = (float*)d_out;

    cudaFuncSetAttribute(accum_kernel,
                         cudaFuncAttributeMaxDynamicSharedMemorySize, SMEM_DYN);

    fused_proj_kernel<<<BB * 16, 128>>>(Kc, RT, pts3d, scale);
    accum_kernel<<<BB * 32, 512, SMEM_DYN>>>(feat, out);
}

// round 15
// speedup vs baseline: 1.2149x; 1.2149x over previous
#include <cuda_runtime.h>
#include <cuda_fp16.h>
#include <cstdint>

// Problem constants: B=4, N=1024, C=16, H=W=128
#define BB 4
#define NN 1024
#define CC 16
#define HW 128

#define EU_STRIDE 72                        // halfwords per padded eu row
#define FT_STRIDE 1032                      // halfwords per padded ft row
#define SEU_OFF   0u                        // 2 x 128 x 72 x 2B = 36864
#define SFT_OFF   36864u                    // 16 x 1032 x 2B   = 33024
#define SEV_OFF   69888u                    // 4 x 1024 x 2B    =  8192
#define SU_OFF    78080u                    // 1024 f32
#define SV_OFF    82176u
#define SSV_OFF   86272u
#define SIDX_OFF  90368u
#define SMEM_DYN  94464u

__device__ __forceinline__ float ex2f(float x) {
    float y;
    asm("ex2.approx.ftz.f32 %0, %1;" : "=f"(y) : "f"(x));
    return y;
}

__device__ __forceinline__ uint32_t smem_u32(const void* p) {
    uint32_t a;
    asm("{ .reg .u64 t; cvta.to.shared.u64 t, %1; cvt.u32.u64 %0, t; }"
        : "=r"(a) : "l"(p));
    return a;
}

__device__ __forceinline__ uint32_t hmul2(uint32_t a, uint32_t b) {
    uint32_t d;
    asm("mul.rn.f16x2 %0, %1, %2;" : "=r"(d) : "r"(a), "r"(b));
    return d;
}

__device__ __forceinline__ void ldsm_x4(uint32_t* r, uint32_t addr) {
    asm volatile("ldmatrix.sync.aligned.m8n8.x4.shared.b16 {%0,%1,%2,%3}, [%4];"
                 : "=r"(r[0]), "=r"(r[1]), "=r"(r[2]), "=r"(r[3]) : "r"(addr));
}

__device__ __forceinline__ void mma16816(float* d, const uint32_t* a,
                                         const uint32_t* b) {
    asm volatile(
        "mma.sync.aligned.m16n8k16.row.col.f32.f16.f16.f32 "
        "{%0,%1,%2,%3}, {%4,%5,%6,%7}, {%8,%9}, {%0,%1,%2,%3};"
        : "+f"(d[0]), "+f"(d[1]), "+f"(d[2]), "+f"(d[3])
        : "r"(a[0]), "r"(a[1]), "r"(a[2]), "r"(a[3]), "r"(b[0]), "r"(b[1]));
}

// Compute one 64-slot euT chunk (f16) into the smem double buffer.
// Thread covers gu row srow = t>>2, slots [k*64 + sq, +16).
__device__ __forceinline__ void compute_eu_chunk(
    char* smem, const float* su, const float* ssv,
    int k, int cnt, int srow, int sq)
{
    const int s0 = k * 64 + sq;
    const float fgu = (float)srow;
    float uu[16], ss[16];
    #pragma unroll
    for (int i = 0; i < 4; i++) {
        *(float4*)&uu[4 * i] = *(const float4*)&su[s0 + 4 * i];
        *(float4*)&ss[4 * i] = *(const float4*)&ssv[s0 + 4 * i];
    }
    uint32_t q[8];
    #pragma unroll
    for (int j = 0; j < 8; j++) {
        float h0 = 0.0f, h1 = 0.0f;
        if (s0 + 2 * j < cnt) {
            float d = uu[2 * j] - fgu;
            h0 = ex2f(d * d * ss[2 * j]);
        }
        if (s0 + 2 * j + 1 < cnt) {
            float d = uu[2 * j + 1] - fgu;
            h1 = ex2f(d * d * ss[2 * j + 1]);
        }
        asm("cvt.rn.f16x2.f32 %0, %1, %2;" : "=r"(q[j]) : "f"(h1), "f"(h0));
    }
    unsigned short* dst = (unsigned short*)(smem + SEU_OFF)
        + (k & 1) * (128 * EU_STRIDE) + srow * EU_STRIDE + sq;
    *(uint4*)dst       = make_uint4(q[0], q[1], q[2], q[3]);
    *(uint4*)(dst + 8) = make_uint4(q[4], q[5], q[6], q[7]);
}

// ---------------------------------------------------------------------------
// SINGLE fused kernel: projection + compaction + factors + HMMA GEMM.
// grid = B*32 = 128 CTAs = (b, 4 gv rows), 512 threads, one wave, no gmem
// scratch. euT chunks are COMPUTED into the smem double buffer each k.
// ---------------------------------------------------------------------------
__global__ void __launch_bounds__(512, 1) fused_kernel(
    const float* __restrict__ Kc,
    const float* __restrict__ RT,
    const float* __restrict__ pts3d,
    const float* __restrict__ feat,
    const float* __restrict__ scale,
    float* __restrict__ out)
{
    extern __shared__ __align__(16) char smem[];
    unsigned short* sft = (unsigned short*)(smem + SFT_OFF);
    unsigned short* sev = (unsigned short*)(smem + SEV_OFF);
    float* su  = (float*)(smem + SU_OFF);
    float* sv  = (float*)(smem + SV_OFF);
    float* ssv = (float*)(smem + SSV_OFF);
    int*   sidx = (int*)(smem + SIDX_OFF);
    __shared__ int wcnt[16];

    const int b   = blockIdx.x >> 5;
    const int gv0 = (blockIdx.x & 31) << 2;
    const int t    = threadIdx.x;
    const int wid  = t >> 5;
    const int lane = t & 31;

    // camera params (broadcast loads)
    const float k0 = Kc[0], k1 = Kc[1], k2 = Kc[2];
    const float k3 = Kc[3], k4 = Kc[4], k5 = Kc[5];
    const float k6 = Kc[6], k7 = Kc[7], k8 = Kc[8];
    const float* rt = RT + b * 12;
    const float r0 = rt[0], r1 = rt[1], r2 = rt[2],  r3  = rt[3];
    const float r4 = rt[4], r5 = rt[5], r6 = rt[6],  r7  = rt[7];
    const float r8 = rt[8], r9 = rt[9], r10 = rt[10], r11 = rt[11];
    const float sig = k0 * 0.03125f;                  // sigma = K[0,0]/32

    // ---- project 2 points/thread + deterministic compaction ----
    int base = 0;
    #pragma unroll
    for (int i = 0; i < 2; i++) {
        const int n = i * 512 + t;
        const float* p = pts3d + ((size_t)b * NN + n) * 3;
        const float p0 = p[0], p1 = p[1], p2 = p[2];
        const float scv = scale[b * NN + n];

        float l0 = r0 * p0 + r1 * p1 + r2  * p2 + r3;
        float l1 = r4 * p0 + r5 * p1 + r6  * p2 + r7;
        float l2 = r8 * p0 + r9 * p1 + r10 * p2 + r11;
        float x = k0 * l0 + k1 * l1 + k2 * l2;
        float y = k3 * l0 + k4 * l1 + k5 * l2;
        float z = k6 * l0 + k7 * l1 + k8 * l2;
        float zc = fmaxf(z, 0.1f);
        float u = x / zc, v = y / zc;
        float s = scv * sig * sig;
        float tt = sqrtf(17.5f * s);                  // f16-exact-zero radius
        bool keep = (z > 0.1f) && (u > -tt) && (u < 127.0f + tt)
                               && (v > -tt) && (v < 127.0f + tt);

        unsigned bal = __ballot_sync(0xffffffffu, keep);
        if (lane == 0) wcnt[wid] = __popc(bal);
        __syncthreads();
        int off = base, tot = 0;
        #pragma unroll
        for (int w = 0; w < 16; w++) {
            const int c_ = wcnt[w];
            tot += c_;
            if (w < wid) off += c_;
        }
        if (keep) {
            const int slot = off + __popc(bal & ((1u << lane) - 1));
            su[slot]  = u;
            sv[slot]  = v;
            ssv[slot] = -1.4426950408889634f / s;     // -log2(e)/s
            sidx[slot] = n;
        }
        base += tot;
        __syncthreads();
    }
    const int cnt = base;
    const int pad = (cnt + 63) & ~63;
    const int nch = pad >> 6;

    // ---- sev: 4 ev rows over compact slots (zeros in pad) ----
    #pragma unroll
    for (int r = 0; r < 4; r++) {
        const float fg = (float)(gv0 + r);
        for (int s = t; s < pad; s += 512) {
            float hv = 0.0f;
            if (s < cnt) {
                float d = sv[s] - fg;
                hv = ex2f(d * d * ssv[s]);
            }
            sev[r * 1024 + s] = __half_as_ushort(__float2half(hv));
        }
    }
    // ---- sft: featT gather via slot index ----
    {
        const int c = t & 15;
        for (int s = t >> 4; s < pad; s += 32) {
            float v = 0.0f;
            if (s < cnt)
                v = feat[((size_t)b * NN + sidx[s]) * CC + c];
            sft[c * FT_STRIDE + s] = __half_as_ushort(__float2half(v));
        }
    }

    // consumer / eu-compute mapping
    const int mt = wid & 7;
    const int rp = wid >> 3;
    const int c0 = (lane & 3) * 2;
    const int srow = t >> 2;
    const int sq   = (t & 3) * 16;

    const unsigned short* evr0 = sev + (rp * 2) * 1024;
    const unsigned short* evr1 = evr0 + 1024;

    const uint32_t sbase = smem_u32(smem);
    const uint32_t euLm0 = sbase + SEU_OFF +
        (uint32_t)(((mt * 16 + (lane & 15)) * EU_STRIDE + (lane >> 4) * 8) * 2);
    const uint32_t ftLm0 = sbase + SFT_OFF +
        (uint32_t)((((lane & 15)) * FT_STRIDE + (lane >> 4) * 8) * 2);

    float acc[2][2][4];
    #pragma unroll
    for (int rr = 0; rr < 2; rr++)
        #pragma unroll
        for (int nt = 0; nt < 2; nt++)
            #pragma unroll
            for (int q = 0; q < 4; q++) acc[rr][nt][q] = 0.0f;

    if (nch > 0) compute_eu_chunk(smem, su, ssv, 0, cnt, srow, sq);
    __syncthreads();

    #pragma unroll 1
    for (int k = 0; k < nch; k++) {
        if (k + 1 < nch)
            compute_eu_chunk(smem, su, ssv, k + 1, cnt, srow, sq);

        const int nb = k * 64;
        const uint32_t euLm = euLm0 + (uint32_t)(k & 1) * (128 * EU_STRIDE * 2);
        const uint32_t ftLm = ftLm0 + (uint32_t)(nb * 2);

        #pragma unroll
        for (int ks = 0; ks < 4; ks++) {
            const int nA = nb + ks * 16 + c0;
            const int nB = nA + 8;

            const uint32_t e0A = *(const uint32_t*)(evr0 + nA);
            const uint32_t e0B = *(const uint32_t*)(evr0 + nB);
            const uint32_t e1A = *(const uint32_t*)(evr1 + nA);
            const uint32_t e1B = *(const uint32_t*)(evr1 + nB);

            uint32_t u[4];
            ldsm_x4(u, euLm + (uint32_t)(ks * 32));

            uint32_t f[4];
            ldsm_x4(f, ftLm + (uint32_t)(ks * 32));
            uint32_t bf0[2] = { f[0], f[2] };
            uint32_t bf1[2] = { f[1], f[3] };

            uint32_t a0[4] = { hmul2(e0A, u[0]), hmul2(e0A, u[1]),
                               hmul2(e0B, u[2]), hmul2(e0B, u[3]) };
            mma16816(acc[0][0], a0, bf0);
            mma16816(acc[0][1], a0, bf1);

            uint32_t a1[4] = { hmul2(e1A, u[0]), hmul2(e1A, u[1]),
                               hmul2(e1B, u[2]), hmul2(e1B, u[3]) };
            mma16816(acc[1][0], a1, bf0);
            mma16816(acc[1][1], a1, bf1);
        }
        __syncthreads();
    }

    // ---- epilogue: D[gu][c] -> out[b][c][gv][gu] ----
    {
        const int guw = mt * 16 + (lane >> 2);
        const int c0w = (lane & 3) * 2;
        #pragma unroll
        for (int rr = 0; rr < 2; rr++) {
            const int gv = gv0 + rp * 2 + rr;
            float* ob = out + (size_t)b * CC * HW * HW + (size_t)gv * HW;
            #pragma unroll
            for (int nt = 0; nt < 2; nt++) {
                const int c = nt * 8 + c0w;
                ob[(size_t)c * HW * HW + guw]           = acc[rr][nt][0];
                ob[(size_t)(c + 1) * HW * HW + guw]     = acc[rr][nt][1];
                ob[(size_t)c * HW * HW + guw + 8]       = acc[rr][nt][2];
                ob[(size_t)(c + 1) * HW * HW + guw + 8] = acc[rr][nt][3];
            }
        }
    }
}

extern "C" void kernel_launch(void* const* d_in, const int* in_sizes, int n_in,
                              void* d_out, int out_size)
{
    const float* Kc    = (const float*)d_in[0];
    const float* RT    = (const float*)d_in[1];
    const float* pts3d = (const float*)d_in[2];
    const float* feat  = (const float*)d_in[3];
    const float* scale = (const float*)d_in[4];
    float* out = (float*)d_out;

    cudaFuncSetAttribute(fused_kernel,
                         cudaFuncAttributeMaxDynamicSharedMemorySize, SMEM_DYN);

    fused_kernel<<<BB * 32, 512, SMEM_DYN>>>(Kc, RT, pts3d, feat, scale, out);
}